// round 10
// baseline (speedup 1.0000x reference)
#include <cuda_runtime.h>
#include <cuda_fp16.h>
#include <cstdint>

#define L_DIM 2048
#define D_DIM 64
#define N_BH 32
#define ROWS 128              // per CTA
#define JT 128
#define NJT (L_DIM / JT)      // 16
#define NTH 256

#define OFF_A 0
#define OFF_B(b) (16384 + (b) * 16384)
#define SMEM_TOTAL 49152

#define NELEM (N_BH * L_DIM * D_DIM)

typedef unsigned long long ull;

__device__ __align__(16) __half g_A[NELEM];
__device__ __align__(16) __half g_B[NELEM];

__device__ __forceinline__ uint32_t smem_u32(const void* p) {
    uint32_t a;
    asm("{ .reg .u64 t; cvta.to.shared.u64 t, %1; cvt.u32.u64 %0, t; }" : "=r"(a) : "l"(p));
    return a;
}
__device__ __forceinline__ float lg2f(float x) {
    float y; asm("lg2.approx.f32 %0, %1;" : "=f"(y) : "f"(x)); return y;
}
__device__ __forceinline__ float ex2f(float x) {
    float y; asm("ex2.approx.f32 %0, %1;" : "=f"(y) : "f"(x)); return y;
}
__device__ __forceinline__ float pow23_mufu(float a) {
    return ex2f(lg2f(fmaxf(a, 0.0f)) * 0.666666667f);
}
__device__ __forceinline__ ull pk2(float lo, float hi) {
    ull r;
    asm("mov.b64 %0, {%1, %2};" : "=l"(r) : "r"(__float_as_uint(lo)), "r"(__float_as_uint(hi)));
    return r;
}
__device__ __forceinline__ void upk2(ull v, float& lo, float& hi) {
    uint32_t a, b;
    asm("mov.b64 {%0, %1}, %2;" : "=r"(a), "=r"(b) : "l"(v));
    lo = __uint_as_float(a); hi = __uint_as_float(b);
}
__device__ __forceinline__ ull mul2(ull a, ull b) {
    ull d; asm("mul.rn.f32x2 %0, %1, %2;" : "=l"(d) : "l"(a), "l"(b)); return d;
}
__device__ __forceinline__ ull fma2p(ull a, ull b, ull c) {
    ull d; asm("fma.rn.f32x2 %0, %1, %2, %3;" : "=l"(d) : "l"(a), "l"(b), "l"(c)); return d;
}
__device__ __forceinline__ void pow23_fma2(float a, float b, float& ya, float& yb) {
    float xa = fmaxf(a, 0.0f), xb = fmaxf(b, 0.0f);
    float wa = __int_as_float(0x54A2FC96 - (__float_as_int(xa) / 3));
    float wb = __int_as_float(0x54A2FC96 - (__float_as_int(xb) / 3));
    ull x2 = pk2(xa, xb), w2 = pk2(wa, wb);
    const ull m13 = pk2(-1.0f / 3.0f, -1.0f / 3.0f);
    const ull f43 = pk2(4.0f / 3.0f, 4.0f / 3.0f);
    ull t2 = mul2(x2, w2);
    ull r2 = mul2(mul2(t2, w2), w2);
    ull u2 = fma2p(r2, m13, f43);
    w2 = mul2(w2, u2);
    t2 = mul2(x2, w2);
    r2 = mul2(mul2(t2, w2), w2);
    u2 = fma2p(r2, m13, f43);
    ull y2 = mul2(t2, u2);
    upk2(y2, ya, yb);
}
__device__ __forceinline__ void ldsm4(uint32_t* r, uint32_t addr) {
    asm volatile("ldmatrix.sync.aligned.m8n8.x4.shared.b16 {%0,%1,%2,%3}, [%4];"
                 : "=r"(r[0]), "=r"(r[1]), "=r"(r[2]), "=r"(r[3]) : "r"(addr));
}
__device__ __forceinline__ void mma16816(float* c, const uint32_t* a, const uint32_t* b) {
    asm volatile(
        "mma.sync.aligned.m16n8k16.row.col.f32.f16.f16.f32 "
        "{%0,%1,%2,%3}, {%4,%5,%6,%7}, {%8,%9}, {%0,%1,%2,%3};"
        : "+f"(c[0]), "+f"(c[1]), "+f"(c[2]), "+f"(c[3])
        : "r"(a[0]), "r"(a[1]), "r"(a[2]), "r"(a[3]), "r"(b[0]), "r"(b[1]));
}
__device__ __forceinline__ void cpa16(uint32_t dst, const void* src) {
    asm volatile("cp.async.cg.shared.global [%0], [%1], 16;" :: "r"(dst), "l"(src) : "memory");
}
__device__ __forceinline__ void cpa_commit() {
    asm volatile("cp.async.commit_group;" ::: "memory");
}
__device__ __forceinline__ void cpa_wait1() {
    asm volatile("cp.async.wait_group 1;" ::: "memory");
}

__global__ void __launch_bounds__(NTH)
prep_kernel(const float* __restrict__ kin, const float* __restrict__ src,
            const float* __restrict__ dst)
{
    int gid = blockIdx.x * NTH + threadIdx.x;
    int rowg = gid >> 2;
    int q = gid & 3;
    int row = rowg & (L_DIM - 1);
    float s = sqrtf(src[rowg] + 1e-12f);
    float d = sqrtf(dst[rowg] + 1e-12f);
    const float* kp = kin + (size_t)rowg * D_DIM + q * 16;
    const int perm = (row & 7) << 3;
    const size_t rbase = (size_t)rowg * D_DIM;

    #pragma unroll
    for (int g = 0; g < 2; ++g) {
        float4 v0 = *(const float4*)(kp + g * 8);
        float4 v1 = *(const float4*)(kp + g * 8 + 4);
        __half2 a0 = __floats2half2_rn(v0.x * s, v0.y * s);
        __half2 a1 = __floats2half2_rn(v0.z * s, v0.w * s);
        __half2 a2 = __floats2half2_rn(v1.x * s, v1.y * s);
        __half2 a3 = __floats2half2_rn(v1.z * s, v1.w * s);
        __half2 b0 = __floats2half2_rn(v0.x * d, v0.y * d);
        __half2 b1 = __floats2half2_rn(v0.z * d, v0.w * d);
        __half2 b2 = __floats2half2_rn(v1.x * d, v1.y * d);
        __half2 b3 = __floats2half2_rn(v1.z * d, v1.w * d);
        int edst = (q * 16 + g * 8) ^ perm;
        *(uint4*)(g_A + rbase + edst) = make_uint4(*(uint32_t*)&a0, *(uint32_t*)&a1,
                                                   *(uint32_t*)&a2, *(uint32_t*)&a3);
        *(uint4*)(g_B + rbase + edst) = make_uint4(*(uint32_t*)&b0, *(uint32_t*)&b1,
                                                   *(uint32_t*)&b2, *(uint32_t*)&b3);
    }
}

__device__ __forceinline__ void copyB(uint32_t sbase, int buf, size_t bbase, int jt, int tid)
{
    #pragma unroll
    for (int it = 0; it < 4; ++it) {
        int idx = tid + it * NTH;
        int row = idx >> 3, seg = idx & 7;
        cpa16(sbase + OFF_B(buf) + (uint32_t)(row * 128 + seg * 16),
              g_B + bbase + (size_t)(jt * JT + row) * D_DIM + seg * 8);
    }
}

__device__ __forceinline__ void unit_pow23(const float* a, int nb,
                                           float& y0, float& y1, float& z0, float& z1) {
    if (nb & 1) {
        pow23_fma2(a[0], a[1], y0, y1);
        pow23_fma2(a[2], a[3], z0, z1);
    } else {
        y0 = pow23_mufu(a[0]); y1 = pow23_mufu(a[1]);
        z0 = pow23_mufu(a[2]); z1 = pow23_mufu(a[3]);
    }
}

__global__ void __launch_bounds__(NTH, 4)
mha_fp16(float* __restrict__ out)
{
    extern __shared__ char smem[];
    const uint32_t sbase = smem_u32(smem);
    const int tid = threadIdx.x;
    const int warp = tid >> 5;
    const int lane = tid & 31;
    const int q = lane & 3;
    const int bh = blockIdx.y;
    // co-residency balance: same-SM CTAs differ in bx by 4 (mod 16)
    const int bxr = blockIdx.x;
    const int low2 = bxr & 3, hi2 = bxr >> 2;
    const int gbase = low2 * 2 + (hi2 >> 1);
    const int bxe = (hi2 & 1) ? (15 - gbase) : gbase;
    const int i0 = bxe * ROWS;

    const size_t khead = (size_t)bh * L_DIM * D_DIM;
    const size_t abase = khead + (size_t)i0 * D_DIM;
    const size_t bbase = khead;

    // A tile: 128 rows x 128B (resident all kernel)
    #pragma unroll
    for (int it = 0; it < 4; ++it) {
        int idx = tid + it * NTH;
        int row = idx >> 3, seg = idx & 7;
        cpa16(sbase + OFF_A + (uint32_t)(row * 128 + seg * 16),
              g_A + abase + (size_t)row * D_DIM + seg * 8);
    }
    copyB(sbase, 0, bbase, 0, tid);
    cpa_commit();
    copyB(sbase, 1, bbase, 1, tid);
    cpa_commit();

    const int rb = warp * 16;
    const int rming = i0 + rb;
    const int dt = i0 >> 7;                   // CTA-uniform diagonal tile idx
    const int ar0 = rb + ((lane >> 3) & 1) * 8 + (lane & 7);
    const int a_kb = ((lane >> 4) & 1) * 16;
    const int ax   = (ar0 & 7) << 4;
    const int br   = ((lane >> 4) & 1) * 8 + (lane & 7);
    const int b_kb = ((lane >> 3) & 1) * 16;
    const int bx2  = (br & 7) << 4;
    const uint32_t a_addr = sbase + OFF_A + ar0 * 128;   // + swizzled k offset per ks

    cpa_wait1();
    __syncthreads();

    const int iu = rming + (lane >> 2);
    const int idn = iu + 8;
    float* const oru_base = out + ((size_t)bh * L_DIM + iu) * L_DIM;
    float* const ord_base = oru_base + 8 * L_DIM;

    float c_up = 0.0f, c_dn = 0.0f;

    for (int jt = 0; jt < NJT; ++jt) {
        if (jt) { cpa_wait1(); __syncthreads(); }
        const uint32_t B = sbase + OFF_B(jt & 1);
        const bool zt = (jt < dt);
        const bool mt = (jt == dt);
        float zu = 0.f, zd = 0.f;

        #pragma unroll
        for (int h = 0; h < 2; ++h) {
            float acc[8][4];
            #pragma unroll
            for (int n = 0; n < 8; ++n)
                #pragma unroll
                for (int c = 0; c < 4; ++c) acc[n][c] = 0.0f;

            #pragma unroll
            for (int ks = 0; ks < 4; ++ks) {
                uint32_t af[4];
                ldsm4(af, a_addr + (((ks * 32) | a_kb) ^ ax));
                const int kb2 = ((ks * 32) | b_kb) ^ bx2;
                #pragma unroll
                for (int cgl = 0; cgl < 4; ++cgl) {
                    const int cg = h * 4 + cgl;
                    uint32_t bf[4];
                    ldsm4(bf, B + (uint32_t)((cg * 16 + br) * 128 + kb2));
                    mma16816(acc[2 * cgl],     af, bf);
                    mma16816(acc[2 * cgl + 1], af, bf + 2);
                }
            }

            if (h == 1) {
                __syncthreads();
                if (jt + 2 < NJT) copyB(sbase, jt & 1, bbase, jt + 2, tid);
                cpa_commit();
            }

            if (zt) {
                #pragma unroll
                for (int nb = 0; nb < 8; ++nb) {
                    float y0, y1, z0, z1;
                    unit_pow23(acc[nb], nb, y0, y1, z0, z1);
                    zu += y0 + y1;
                    zd += z0 + z1;
                }
            } else if (mt) {
                #pragma unroll
                for (int nb = 0; nb < 8; ++nb) {
                    const int j0 = jt * JT + h * 64 + nb * 8 + q * 2;
                    float y0, y1, z0, z1;
                    unit_pow23(acc[nb], nb, y0, y1, z0, z1);
                    {
                        float v = y0 + y1, sc = v;
                        float u1 = __shfl_up_sync(0xffffffffu, sc, 1, 4); if (q >= 1) sc += u1;
                        float u2 = __shfl_up_sync(0xffffffffu, sc, 2, 4); if (q >= 2) sc += u2;
                        float tot = __shfl_sync(0xffffffffu, sc, 3, 4);
                        float base = c_up + (sc - v);
                        float2 o;
                        o.x = (j0     >= iu) ? base + y0 : 0.0f;
                        o.y = (j0 + 1 >= iu) ? base + v  : 0.0f;
                        *(float2*)(oru_base + j0) = o;
                        c_up += tot;
                    }
                    {
                        float v = z0 + z1, sc = v;
                        float u1 = __shfl_up_sync(0xffffffffu, sc, 1, 4); if (q >= 1) sc += u1;
                        float u2 = __shfl_up_sync(0xffffffffu, sc, 2, 4); if (q >= 2) sc += u2;
                        float tot = __shfl_sync(0xffffffffu, sc, 3, 4);
                        float base = c_dn + (sc - v);
                        float2 o;
                        o.x = (j0     >= idn) ? base + z0 : 0.0f;
                        o.y = (j0 + 1 >= idn) ? base + v  : 0.0f;
                        *(float2*)(ord_base + j0) = o;
                        c_dn += tot;
                    }
                }
            } else {
                #pragma unroll
                for (int nb = 0; nb < 8; ++nb) {
                    const int j0 = jt * JT + h * 64 + nb * 8 + q * 2;
                    float y0, y1, z0, z1;
                    unit_pow23(acc[nb], nb, y0, y1, z0, z1);
                    {
                        float v = y0 + y1, sc = v;
                        float u1 = __shfl_up_sync(0xffffffffu, sc, 1, 4); if (q >= 1) sc += u1;
                        float u2 = __shfl_up_sync(0xffffffffu, sc, 2, 4); if (q >= 2) sc += u2;
                        float tot = __shfl_sync(0xffffffffu, sc, 3, 4);
                        float base = c_up + (sc - v);
                        float2 o; o.x = base + y0; o.y = base + v;
                        *(float2*)(oru_base + j0) = o;
                        c_up += tot;
                    }
                    {
                        float v = z0 + z1, sc = v;
                        float u1 = __shfl_up_sync(0xffffffffu, sc, 1, 4); if (q >= 1) sc += u1;
                        float u2 = __shfl_up_sync(0xffffffffu, sc, 2, 4); if (q >= 2) sc += u2;
                        float tot = __shfl_sync(0xffffffffu, sc, 3, 4);
                        float base = c_dn + (sc - v);
                        float2 o; o.x = base + z0; o.y = base + v;
                        *(float2*)(ord_base + j0) = o;
                        c_dn += tot;
                    }
                }
            }
        }

        if (zt) {
            float t = zu;
            t += __shfl_xor_sync(0xffffffffu, t, 1, 4);
            t += __shfl_xor_sync(0xffffffffu, t, 2, 4);
            c_up += t;
            float s2 = zd;
            s2 += __shfl_xor_sync(0xffffffffu, s2, 1, 4);
            s2 += __shfl_xor_sync(0xffffffffu, s2, 2, 4);
            c_dn += s2;
            float4 z4 = make_float4(0.f, 0.f, 0.f, 0.f);
            float* obase = out + ((size_t)bh * L_DIM + rming) * L_DIM + jt * JT + lane * 4;
            #pragma unroll 4
            for (int r = 0; r < 16; ++r)
                *(float4*)(obase + (size_t)r * L_DIM) = z4;
        }
    }
}

extern "C" void kernel_launch(void* const* d_in, const int* in_sizes, int n_in,
                              void* d_out, int out_size) {
    const float* k    = (const float*)d_in[0];
    const float* src  = (const float*)d_in[1];
    const float* dest = (const float*)d_in[2];
    float* out = (float*)d_out;

    prep_kernel<<<(N_BH * L_DIM * 4) / NTH, NTH>>>(k, src, dest);

    cudaFuncSetAttribute(mha_fp16,
                         cudaFuncAttributeMaxDynamicSharedMemorySize, SMEM_TOTAL);
    dim3 grid(16, N_BH);   // 512 CTAs -> one wave at 4 CTAs/SM
    mha_fp16<<<grid, NTH, SMEM_TOTAL>>>(out);
}

// round 11
// speedup vs baseline: 1.0623x; 1.0623x over previous
#include <cuda_runtime.h>
#include <cuda_fp16.h>
#include <cstdint>

#define L_DIM 2048
#define D_DIM 64
#define N_BH 32
#define ROWS 128
#define JT 128
#define NJT (L_DIM / JT)
#define NTH 256

#define OFF_A 0
#define OFF_B(b) (16384 + (b) * 16384)
#define SMEM_TOTAL 49152

#define NELEM (N_BH * L_DIM * D_DIM)

typedef unsigned long long ull;

__device__ __align__(16) __half g_A[NELEM];
__device__ __align__(16) __half g_B[NELEM];

__device__ __forceinline__ uint32_t smem_u32(const void* p) {
    uint32_t a;
    asm("{ .reg .u64 t; cvta.to.shared.u64 t, %1; cvt.u32.u64 %0, t; }" : "=r"(a) : "l"(p));
    return a;
}
__device__ __forceinline__ float lg2f(float x) {
    float y; asm("lg2.approx.f32 %0, %1;" : "=f"(y) : "f"(x)); return y;
}
__device__ __forceinline__ float ex2f(float x) {
    float y; asm("ex2.approx.f32 %0, %1;" : "=f"(y) : "f"(x)); return y;
}
__device__ __forceinline__ float pow23_mufu(float a) {
    return ex2f(lg2f(fmaxf(a, 0.0f)) * 0.666666667f);
}
__device__ __forceinline__ ull pk2(float lo, float hi) {
    ull r;
    asm("mov.b64 %0, {%1, %2};" : "=l"(r) : "r"(__float_as_uint(lo)), "r"(__float_as_uint(hi)));
    return r;
}
__device__ __forceinline__ void upk2(ull v, float& lo, float& hi) {
    uint32_t a, b;
    asm("mov.b64 {%0, %1}, %2;" : "=r"(a), "=r"(b) : "l"(v));
    lo = __uint_as_float(a); hi = __uint_as_float(b);
}
__device__ __forceinline__ ull mul2(ull a, ull b) {
    ull d; asm("mul.rn.f32x2 %0, %1, %2;" : "=l"(d) : "l"(a), "l"(b)); return d;
}
__device__ __forceinline__ ull fma2p(ull a, ull b, ull c) {
    ull d; asm("fma.rn.f32x2 %0, %1, %2, %3;" : "=l"(d) : "l"(a), "l"(b), "l"(c)); return d;
}
__device__ __forceinline__ void pow23_fma2(float a, float b, float& ya, float& yb) {
    float xa = fmaxf(a, 0.0f), xb = fmaxf(b, 0.0f);
    float wa = __int_as_float(0x54A2FC96 - (__float_as_int(xa) / 3));
    float wb = __int_as_float(0x54A2FC96 - (__float_as_int(xb) / 3));
    ull x2 = pk2(xa, xb), w2 = pk2(wa, wb);
    const ull m13 = pk2(-1.0f / 3.0f, -1.0f / 3.0f);
    const ull f43 = pk2(4.0f / 3.0f, 4.0f / 3.0f);
    ull t2 = mul2(x2, w2);
    ull r2 = mul2(mul2(t2, w2), w2);
    ull u2 = fma2p(r2, m13, f43);
    w2 = mul2(w2, u2);
    t2 = mul2(x2, w2);
    r2 = mul2(mul2(t2, w2), w2);
    u2 = fma2p(r2, m13, f43);
    ull y2 = mul2(t2, u2);
    upk2(y2, ya, yb);
}
__device__ __forceinline__ void ldsm4(uint32_t* r, uint32_t addr) {
    asm volatile("ldmatrix.sync.aligned.m8n8.x4.shared.b16 {%0,%1,%2,%3}, [%4];"
                 : "=r"(r[0]), "=r"(r[1]), "=r"(r[2]), "=r"(r[3]) : "r"(addr));
}
__device__ __forceinline__ void mma16816(float* c, const uint32_t* a, const uint32_t* b) {
    asm volatile(
        "mma.sync.aligned.m16n8k16.row.col.f32.f16.f16.f32 "
        "{%0,%1,%2,%3}, {%4,%5,%6,%7}, {%8,%9}, {%0,%1,%2,%3};"
        : "+f"(c[0]), "+f"(c[1]), "+f"(c[2]), "+f"(c[3])
        : "r"(a[0]), "r"(a[1]), "r"(a[2]), "r"(a[3]), "r"(b[0]), "r"(b[1]));
}
__device__ __forceinline__ void cpa16(uint32_t dst, const void* src) {
    asm volatile("cp.async.cg.shared.global [%0], [%1], 16;" :: "r"(dst), "l"(src) : "memory");
}
__device__ __forceinline__ void cpa_commit() {
    asm volatile("cp.async.commit_group;" ::: "memory");
}
__device__ __forceinline__ void cpa_wait1() {
    asm volatile("cp.async.wait_group 1;" ::: "memory");
}

__global__ void __launch_bounds__(NTH)
prep_kernel(const float* __restrict__ kin, const float* __restrict__ src,
            const float* __restrict__ dst)
{
    int gid = blockIdx.x * NTH + threadIdx.x;
    int rowg = gid >> 2;
    int q = gid & 3;
    int row = rowg & (L_DIM - 1);
    float s = sqrtf(src[rowg] + 1e-12f);
    float d = sqrtf(dst[rowg] + 1e-12f);
    const float* kp = kin + (size_t)rowg * D_DIM + q * 16;
    const int perm = (row & 7) << 3;
    const size_t rbase = (size_t)rowg * D_DIM;

    #pragma unroll
    for (int g = 0; g < 2; ++g) {
        float4 v0 = *(const float4*)(kp + g * 8);
        float4 v1 = *(const float4*)(kp + g * 8 + 4);
        __half2 a0 = __floats2half2_rn(v0.x * s, v0.y * s);
        __half2 a1 = __floats2half2_rn(v0.z * s, v0.w * s);
        __half2 a2 = __floats2half2_rn(v1.x * s, v1.y * s);
        __half2 a3 = __floats2half2_rn(v1.z * s, v1.w * s);
        __half2 b0 = __floats2half2_rn(v0.x * d, v0.y * d);
        __half2 b1 = __floats2half2_rn(v0.z * d, v0.w * d);
        __half2 b2 = __floats2half2_rn(v1.x * d, v1.y * d);
        __half2 b3 = __floats2half2_rn(v1.z * d, v1.w * d);
        int edst = (q * 16 + g * 8) ^ perm;
        *(uint4*)(g_A + rbase + edst) = make_uint4(*(uint32_t*)&a0, *(uint32_t*)&a1,
                                                   *(uint32_t*)&a2, *(uint32_t*)&a3);
        *(uint4*)(g_B + rbase + edst) = make_uint4(*(uint32_t*)&b0, *(uint32_t*)&b1,
                                                   *(uint32_t*)&b2, *(uint32_t*)&b3);
    }
}

__device__ __forceinline__ void copyB(uint32_t sbase, int buf, size_t bbase, int jt, int tid)
{
    #pragma unroll
    for (int it = 0; it < 4; ++it) {
        int idx = tid + it * NTH;
        int row = idx >> 3, seg = idx & 7;
        cpa16(sbase + OFF_B(buf) + (uint32_t)(row * 128 + seg * 16),
              g_B + bbase + (size_t)(jt * JT + row) * D_DIM + seg * 8);
    }
}

// Repack pair of n8 units (16 cols) so lane q owns 4 consecutive cols, then
// in-lane prefix + width-4 scan + carry, optional causal mask, one STG.128.
template <bool MASK>
__device__ __forceinline__ void pair_scan_store(
    float va0, float va1, float vb0, float vb1,
    float& carry, float* rowp, int c0, int irow, int q)
{
    const unsigned F = 0xffffffffu;
    float t0 = __shfl_sync(F, va0, 2 * q,     4);
    float t1 = __shfl_sync(F, va1, 2 * q,     4);
    float t2 = __shfl_sync(F, va0, 2 * q + 1, 4);
    float t3 = __shfl_sync(F, va1, 2 * q + 1, 4);
    float u0 = __shfl_sync(F, vb0, 2 * q,     4);
    float u1 = __shfl_sync(F, vb1, 2 * q,     4);
    float u2 = __shfl_sync(F, vb0, 2 * q + 1, 4);
    float u3 = __shfl_sync(F, vb1, 2 * q + 1, 4);
    bool hi = (q >= 2);
    float x0 = hi ? u0 : t0;
    float x1 = hi ? u1 : t1;
    float x2 = hi ? u2 : t2;
    float x3 = hi ? u3 : t3;
    float p1 = x0 + x1;
    float p2 = p1 + x2;
    float p3 = p2 + x3;
    float sc = p3;
    float s1 = __shfl_up_sync(F, sc, 1, 4); if (q >= 1) sc += s1;
    float s2 = __shfl_up_sync(F, sc, 2, 4); if (q >= 2) sc += s2;
    float tot = __shfl_sync(F, sc, 3, 4);
    float base = carry + (sc - p3);
    carry += tot;
    const int cq = c0 + q * 4;
    float4 o;
    if (MASK) {
        o.x = (cq     >= irow) ? base + x0 : 0.0f;
        o.y = (cq + 1 >= irow) ? base + p1 : 0.0f;
        o.z = (cq + 2 >= irow) ? base + p2 : 0.0f;
        o.w = (cq + 3 >= irow) ? base + p3 : 0.0f;
    } else {
        o.x = base + x0; o.y = base + p1; o.z = base + p2; o.w = base + p3;
    }
    *(float4*)(rowp + cq) = o;
}

__global__ void __launch_bounds__(NTH, 3)
mha_fp16(float* __restrict__ out)
{
    extern __shared__ char smem[];
    const uint32_t sbase = smem_u32(smem);
    const int tid = threadIdx.x;
    const int warp = tid >> 5;
    const int lane = tid & 31;
    const int q = lane & 3;
    const int bh = blockIdx.y;
    const int bxr = blockIdx.x;
    const int low2 = bxr & 3, hi2 = bxr >> 2;
    const int gbase = low2 * 2 + (hi2 >> 1);
    const int bxe = (hi2 & 1) ? (15 - gbase) : gbase;
    const int i0 = bxe * ROWS;

    const size_t khead = (size_t)bh * L_DIM * D_DIM;
    const size_t abase = khead + (size_t)i0 * D_DIM;
    const size_t bbase = khead;

    #pragma unroll
    for (int it = 0; it < 4; ++it) {
        int idx = tid + it * NTH;
        int row = idx >> 3, seg = idx & 7;
        cpa16(sbase + OFF_A + (uint32_t)(row * 128 + seg * 16),
              g_A + abase + (size_t)row * D_DIM + seg * 8);
    }
    copyB(sbase, 0, bbase, 0, tid);
    cpa_commit();
    copyB(sbase, 1, bbase, 1, tid);
    cpa_commit();

    const int rb = warp * 16;
    const int rming = i0 + rb;
    const int dt = i0 >> 7;
    const int ar0 = rb + ((lane >> 3) & 1) * 8 + (lane & 7);
    const int a_kb = ((lane >> 4) & 1) * 16;
    const int ax   = (ar0 & 7) << 4;
    const int br   = ((lane >> 4) & 1) * 8 + (lane & 7);
    const int b_kb = ((lane >> 3) & 1) * 16;
    const int bx2  = (br & 7) << 4;

    cpa_wait1();
    __syncthreads();

    uint32_t afr[4][4];
    #pragma unroll
    for (int ks = 0; ks < 4; ++ks)
        ldsm4(afr[ks], sbase + OFF_A + ar0 * 128 + (((ks * 32) | a_kb) ^ ax));

    const int iu = rming + (lane >> 2);
    const int idn = iu + 8;
    float* const oru_base = out + ((size_t)bh * L_DIM + iu) * L_DIM;
    float* const ord_base = oru_base + 8 * L_DIM;

    float c_up = 0.0f, c_dn = 0.0f;

    for (int jt = 0; jt < NJT; ++jt) {
        if (jt) { cpa_wait1(); __syncthreads(); }
        const uint32_t B = sbase + OFF_B(jt & 1);
        const bool zt = (jt < dt);
        const bool mt = (jt == dt);
        float zu = 0.f, zd = 0.f;

        #pragma unroll
        for (int h = 0; h < 2; ++h) {
            float acc[8][4];
            #pragma unroll
            for (int n = 0; n < 8; ++n)
                #pragma unroll
                for (int c = 0; c < 4; ++c) acc[n][c] = 0.0f;

            #pragma unroll
            for (int ks = 0; ks < 4; ++ks) {
                const int kb2 = ((ks * 32) | b_kb) ^ bx2;
                #pragma unroll
                for (int cgl = 0; cgl < 4; ++cgl) {
                    const int cg = h * 4 + cgl;
                    uint32_t bf[4];
                    ldsm4(bf, B + (uint32_t)((cg * 16 + br) * 128 + kb2));
                    mma16816(acc[2 * cgl],     afr[ks], bf);
                    mma16816(acc[2 * cgl + 1], afr[ks], bf + 2);
                }
            }

            if (h == 1) {
                __syncthreads();
                if (jt + 2 < NJT) copyB(sbase, jt & 1, bbase, jt + 2, tid);
                cpa_commit();
            }

            if (zt) {
                #pragma unroll
                for (int nb = 0; nb < 8; ++nb) {
                    float y0, y1, z0, z1;
                    if (nb & 1) {
                        pow23_fma2(acc[nb][0], acc[nb][1], y0, y1);
                        pow23_fma2(acc[nb][2], acc[nb][3], z0, z1);
                    } else {
                        y0 = pow23_mufu(acc[nb][0]); y1 = pow23_mufu(acc[nb][1]);
                        z0 = pow23_mufu(acc[nb][2]); z1 = pow23_mufu(acc[nb][3]);
                    }
                    zu += y0 + y1;
                    zd += z0 + z1;
                }
            } else {
                #pragma unroll
                for (int nb = 0; nb < 8; nb += 2) {
                    // unit nb on MUFU pipe, unit nb+1 on FMA pipe
                    float ya0 = pow23_mufu(acc[nb][0]);
                    float ya1 = pow23_mufu(acc[nb][1]);
                    float za0 = pow23_mufu(acc[nb][2]);
                    float za1 = pow23_mufu(acc[nb][3]);
                    float yb0, yb1, zb0, zb1;
                    pow23_fma2(acc[nb + 1][0], acc[nb + 1][1], yb0, yb1);
                    pow23_fma2(acc[nb + 1][2], acc[nb + 1][3], zb0, zb1);
                    const int c0 = jt * JT + h * 64 + nb * 8;
                    if (mt) {
                        pair_scan_store<true>(ya0, ya1, yb0, yb1, c_up, oru_base, c0, iu, q);
                        pair_scan_store<true>(za0, za1, zb0, zb1, c_dn, ord_base, c0, idn, q);
                    } else {
                        pair_scan_store<false>(ya0, ya1, yb0, yb1, c_up, oru_base, c0, iu, q);
                        pair_scan_store<false>(za0, za1, zb0, zb1, c_dn, ord_base, c0, idn, q);
                    }
                }
            }
        }

        if (zt) {
            float t = zu;
            t += __shfl_xor_sync(0xffffffffu, t, 1, 4);
            t += __shfl_xor_sync(0xffffffffu, t, 2, 4);
            c_up += t;
            float s2 = zd;
            s2 += __shfl_xor_sync(0xffffffffu, s2, 1, 4);
            s2 += __shfl_xor_sync(0xffffffffu, s2, 2, 4);
            c_dn += s2;
            float4 z4 = make_float4(0.f, 0.f, 0.f, 0.f);
            float* obase = out + ((size_t)bh * L_DIM + rming) * L_DIM + jt * JT + lane * 4;
            #pragma unroll 4
            for (int r = 0; r < 16; ++r)
                *(float4*)(obase + (size_t)r * L_DIM) = z4;
        }
    }
}

extern "C" void kernel_launch(void* const* d_in, const int* in_sizes, int n_in,
                              void* d_out, int out_size) {
    const float* k    = (const float*)d_in[0];
    const float* src  = (const float*)d_in[1];
    const float* dest = (const float*)d_in[2];
    float* out = (float*)d_out;

    prep_kernel<<<(N_BH * L_DIM * 4) / NTH, NTH>>>(k, src, dest);

    cudaFuncSetAttribute(mha_fp16,
                         cudaFuncAttributeMaxDynamicSharedMemorySize, SMEM_TOTAL);
    dim3 grid(16, N_BH);
    mha_fp16<<<grid, NTH, SMEM_TOTAL>>>(out);
}

// round 12
// speedup vs baseline: 1.0763x; 1.0132x over previous
#include <cuda_runtime.h>
#include <cuda_fp16.h>
#include <cstdint>

#define L_DIM 2048
#define D_DIM 64
#define N_BH 32
#define ROWS 128
#define JT 128
#define NJT (L_DIM / JT)
#define NTH 256

#define OFF_A 0
#define OFF_B(b) (16384 + (b) * 16384)
#define SMEM_TOTAL 49152

#define NELEM (N_BH * L_DIM * D_DIM)

typedef unsigned long long ull;

__device__ __align__(16) __half g_A[NELEM];
__device__ __align__(16) __half g_B[NELEM];

__device__ __forceinline__ uint32_t smem_u32(const void* p) {
    uint32_t a;
    asm("{ .reg .u64 t; cvta.to.shared.u64 t, %1; cvt.u32.u64 %0, t; }" : "=r"(a) : "l"(p));
    return a;
}
__device__ __forceinline__ float lg2f(float x) {
    float y; asm("lg2.approx.f32 %0, %1;" : "=f"(y) : "f"(x)); return y;
}
__device__ __forceinline__ float ex2f(float x) {
    float y; asm("ex2.approx.f32 %0, %1;" : "=f"(y) : "f"(x)); return y;
}
__device__ __forceinline__ float pow23_mufu(float a) {
    return ex2f(lg2f(fmaxf(a, 0.0f)) * 0.666666667f);
}
__device__ __forceinline__ ull pk2(float lo, float hi) {
    ull r;
    asm("mov.b64 %0, {%1, %2};" : "=l"(r) : "r"(__float_as_uint(lo)), "r"(__float_as_uint(hi)));
    return r;
}
__device__ __forceinline__ void upk2(ull v, float& lo, float& hi) {
    uint32_t a, b;
    asm("mov.b64 {%0, %1}, %2;" : "=r"(a), "=r"(b) : "l"(v));
    lo = __uint_as_float(a); hi = __uint_as_float(b);
}
__device__ __forceinline__ ull mul2(ull a, ull b) {
    ull d; asm("mul.rn.f32x2 %0, %1, %2;" : "=l"(d) : "l"(a), "l"(b)); return d;
}
__device__ __forceinline__ ull fma2p(ull a, ull b, ull c) {
    ull d; asm("fma.rn.f32x2 %0, %1, %2, %3;" : "=l"(d) : "l"(a), "l"(b), "l"(c)); return d;
}
__device__ __forceinline__ void pow23_fma2(float a, float b, float& ya, float& yb) {
    float xa = fmaxf(a, 0.0f), xb = fmaxf(b, 0.0f);
    float wa = __int_as_float(0x54A2FC96 - (__float_as_int(xa) / 3));
    float wb = __int_as_float(0x54A2FC96 - (__float_as_int(xb) / 3));
    ull x2 = pk2(xa, xb), w2 = pk2(wa, wb);
    const ull m13 = pk2(-1.0f / 3.0f, -1.0f / 3.0f);
    const ull f43 = pk2(4.0f / 3.0f, 4.0f / 3.0f);
    ull t2 = mul2(x2, w2);
    ull r2 = mul2(mul2(t2, w2), w2);
    ull u2 = fma2p(r2, m13, f43);
    w2 = mul2(w2, u2);
    t2 = mul2(x2, w2);
    r2 = mul2(mul2(t2, w2), w2);
    u2 = fma2p(r2, m13, f43);
    ull y2 = mul2(t2, u2);
    upk2(y2, ya, yb);
}
__device__ __forceinline__ void ldsm4(uint32_t* r, uint32_t addr) {
    asm volatile("ldmatrix.sync.aligned.m8n8.x4.shared.b16 {%0,%1,%2,%3}, [%4];"
                 : "=r"(r[0]), "=r"(r[1]), "=r"(r[2]), "=r"(r[3]) : "r"(addr));
}
__device__ __forceinline__ void mma16816(float* c, const uint32_t* a, const uint32_t* b) {
    asm volatile(
        "mma.sync.aligned.m16n8k16.row.col.f32.f16.f16.f32 "
        "{%0,%1,%2,%3}, {%4,%5,%6,%7}, {%8,%9}, {%0,%1,%2,%3};"
        : "+f"(c[0]), "+f"(c[1]), "+f"(c[2]), "+f"(c[3])
        : "r"(a[0]), "r"(a[1]), "r"(a[2]), "r"(a[3]), "r"(b[0]), "r"(b[1]));
}
__device__ __forceinline__ void cpa16(uint32_t dst, const void* src) {
    asm volatile("cp.async.cg.shared.global [%0], [%1], 16;" :: "r"(dst), "l"(src) : "memory");
}
__device__ __forceinline__ void cpa_commit() {
    asm volatile("cp.async.commit_group;" ::: "memory");
}
__device__ __forceinline__ void cpa_wait1() {
    asm volatile("cp.async.wait_group 1;" ::: "memory");
}

__global__ void __launch_bounds__(NTH)
prep_kernel(const float* __restrict__ kin, const float* __restrict__ src,
            const float* __restrict__ dst)
{
    int gid = blockIdx.x * NTH + threadIdx.x;
    int rowg = gid >> 2;
    int q = gid & 3;
    int row = rowg & (L_DIM - 1);
    float s = sqrtf(src[rowg] + 1e-12f);
    float d = sqrtf(dst[rowg] + 1e-12f);
    const float* kp = kin + (size_t)rowg * D_DIM + q * 16;
    const int perm = (row & 7) << 3;
    const size_t rbase = (size_t)rowg * D_DIM;

    #pragma unroll
    for (int g = 0; g < 2; ++g) {
        float4 v0 = *(const float4*)(kp + g * 8);
        float4 v1 = *(const float4*)(kp + g * 8 + 4);
        __half2 a0 = __floats2half2_rn(v0.x * s, v0.y * s);
        __half2 a1 = __floats2half2_rn(v0.z * s, v0.w * s);
        __half2 a2 = __floats2half2_rn(v1.x * s, v1.y * s);
        __half2 a3 = __floats2half2_rn(v1.z * s, v1.w * s);
        __half2 b0 = __floats2half2_rn(v0.x * d, v0.y * d);
        __half2 b1 = __floats2half2_rn(v0.z * d, v0.w * d);
        __half2 b2 = __floats2half2_rn(v1.x * d, v1.y * d);
        __half2 b3 = __floats2half2_rn(v1.z * d, v1.w * d);
        int edst = (q * 16 + g * 8) ^ perm;
        *(uint4*)(g_A + rbase + edst) = make_uint4(*(uint32_t*)&a0, *(uint32_t*)&a1,
                                                   *(uint32_t*)&a2, *(uint32_t*)&a3);
        *(uint4*)(g_B + rbase + edst) = make_uint4(*(uint32_t*)&b0, *(uint32_t*)&b1,
                                                   *(uint32_t*)&b2, *(uint32_t*)&b3);
    }
}

__device__ __forceinline__ void copyB(uint32_t sbase, int buf, size_t bbase, int jt, int tid)
{
    #pragma unroll
    for (int it = 0; it < 4; ++it) {
        int idx = tid + it * NTH;
        int row = idx >> 3, seg = idx & 7;
        cpa16(sbase + OFF_B(buf) + (uint32_t)(row * 128 + seg * 16),
              g_B + bbase + (size_t)(jt * JT + row) * D_DIM + seg * 8);
    }
}

// Phase-structured scan+store for one row-half (8 units x 8 cols):
// all unit scans are independent (pipelined shfls); only 8 FADDs are serial.
template <bool MASK>
__device__ __forceinline__ void half_epilogue(
    const float (*acc)[4], int ci,              // ci: 0 for up (acc[.][0..1]), 2 for dn
    float& carry, float* rowp, int jbase, int irow, int q)
{
    const unsigned F = 0xffffffffu;
    float y1s[8], sc[8], C[8];
    // phase 1: pow23 + pair sums (alternating pipes by unit parity)
    #pragma unroll
    for (int nb = 0; nb < 8; ++nb) {
        float y0, y1;
        if (nb & 1) pow23_fma2(acc[nb][ci], acc[nb][ci + 1], y0, y1);
        else { y0 = pow23_mufu(acc[nb][ci]); y1 = pow23_mufu(acc[nb][ci + 1]); }
        y1s[nb] = y1;
        sc[nb] = y0 + y1;
    }
    // phase 2: independent width-4 inclusive scans
    #pragma unroll
    for (int nb = 0; nb < 8; ++nb) {
        float s1 = __shfl_up_sync(F, sc[nb], 1, 4); if (q >= 1) sc[nb] += s1;
        float s2 = __shfl_up_sync(F, sc[nb], 2, 4); if (q >= 2) sc[nb] += s2;
    }
    // phase 3: independent totals
    #pragma unroll
    for (int nb = 0; nb < 8; ++nb)
        C[nb] = __shfl_sync(F, sc[nb], 3, 4);
    // phase 4: serial base chain (FADD-only) + stores
    float base = carry;
    #pragma unroll
    for (int nb = 0; nb < 8; ++nb) {
        const int j0 = jbase + nb * 8 + q * 2;
        float2 o;
        if (MASK) {
            o.x = (j0     >= irow) ? base + sc[nb] - y1s[nb] : 0.0f;
            o.y = (j0 + 1 >= irow) ? base + sc[nb]           : 0.0f;
        } else {
            o.x = base + sc[nb] - y1s[nb];
            o.y = base + sc[nb];
        }
        *(float2*)(rowp + j0) = o;
        base += C[nb];
    }
    carry = base;
}

__global__ void __launch_bounds__(NTH, 3)
mha_fp16(float* __restrict__ out)
{
    extern __shared__ char smem[];
    const uint32_t sbase = smem_u32(smem);
    const int tid = threadIdx.x;
    const int warp = tid >> 5;
    const int lane = tid & 31;
    const int q = lane & 3;
    const int bh = blockIdx.y;
    const int bxr = blockIdx.x;
    const int low2 = bxr & 3, hi2 = bxr >> 2;
    const int gbase = low2 * 2 + (hi2 >> 1);
    const int bxe = (hi2 & 1) ? (15 - gbase) : gbase;
    const int i0 = bxe * ROWS;

    const size_t khead = (size_t)bh * L_DIM * D_DIM;
    const size_t abase = khead + (size_t)i0 * D_DIM;
    const size_t bbase = khead;

    #pragma unroll
    for (int it = 0; it < 4; ++it) {
        int idx = tid + it * NTH;
        int row = idx >> 3, seg = idx & 7;
        cpa16(sbase + OFF_A + (uint32_t)(row * 128 + seg * 16),
              g_A + abase + (size_t)row * D_DIM + seg * 8);
    }
    copyB(sbase, 0, bbase, 0, tid);
    cpa_commit();
    copyB(sbase, 1, bbase, 1, tid);
    cpa_commit();

    const int rb = warp * 16;
    const int rming = i0 + rb;
    const int dt = i0 >> 7;
    const int ar0 = rb + ((lane >> 3) & 1) * 8 + (lane & 7);
    const int a_kb = ((lane >> 4) & 1) * 16;
    const int ax   = (ar0 & 7) << 4;
    const int br   = ((lane >> 4) & 1) * 8 + (lane & 7);
    const int b_kb = ((lane >> 3) & 1) * 16;
    const int bx2  = (br & 7) << 4;

    cpa_wait1();
    __syncthreads();

    uint32_t afr[4][4];
    #pragma unroll
    for (int ks = 0; ks < 4; ++ks)
        ldsm4(afr[ks], sbase + OFF_A + ar0 * 128 + (((ks * 32) | a_kb) ^ ax));

    const int iu = rming + (lane >> 2);
    const int idn = iu + 8;
    float* const oru_base = out + ((size_t)bh * L_DIM + iu) * L_DIM;
    float* const ord_base = oru_base + 8 * L_DIM;

    float c_up = 0.0f, c_dn = 0.0f;

    for (int jt = 0; jt < NJT; ++jt) {
        if (jt) { cpa_wait1(); __syncthreads(); }
        const uint32_t B = sbase + OFF_B(jt & 1);
        const bool zt = (jt < dt);
        const bool mt = (jt == dt);
        float zu = 0.f, zd = 0.f;

        #pragma unroll
        for (int h = 0; h < 2; ++h) {
            float acc[8][4];
            #pragma unroll
            for (int n = 0; n < 8; ++n)
                #pragma unroll
                for (int c = 0; c < 4; ++c) acc[n][c] = 0.0f;

            #pragma unroll
            for (int ks = 0; ks < 4; ++ks) {
                const int kb2 = ((ks * 32) | b_kb) ^ bx2;
                #pragma unroll
                for (int cgl = 0; cgl < 4; ++cgl) {
                    const int cg = h * 4 + cgl;
                    uint32_t bf[4];
                    ldsm4(bf, B + (uint32_t)((cg * 16 + br) * 128 + kb2));
                    mma16816(acc[2 * cgl],     afr[ks], bf);
                    mma16816(acc[2 * cgl + 1], afr[ks], bf + 2);
                }
            }

            if (h == 1) {
                __syncthreads();
                if (jt + 2 < NJT) copyB(sbase, jt & 1, bbase, jt + 2, tid);
                cpa_commit();
            }

            if (zt) {
                #pragma unroll
                for (int nb = 0; nb < 8; ++nb) {
                    float y0, y1, z0, z1;
                    if (nb & 1) {
                        pow23_fma2(acc[nb][0], acc[nb][1], y0, y1);
                        pow23_fma2(acc[nb][2], acc[nb][3], z0, z1);
                    } else {
                        y0 = pow23_mufu(acc[nb][0]); y1 = pow23_mufu(acc[nb][1]);
                        z0 = pow23_mufu(acc[nb][2]); z1 = pow23_mufu(acc[nb][3]);
                    }
                    zu += y0 + y1;
                    zd += z0 + z1;
                }
            } else {
                const int jbase = jt * JT + h * 64;
                if (mt) {
                    half_epilogue<true>(acc, 0, c_up, oru_base, jbase, iu, q);
                    half_epilogue<true>(acc, 2, c_dn, ord_base, jbase, idn, q);
                } else {
                    half_epilogue<false>(acc, 0, c_up, oru_base, jbase, iu, q);
                    half_epilogue<false>(acc, 2, c_dn, ord_base, jbase, idn, q);
                }
            }
        }

        if (zt) {
            float t = zu;
            t += __shfl_xor_sync(0xffffffffu, t, 1, 4);
            t += __shfl_xor_sync(0xffffffffu, t, 2, 4);
            c_up += t;
            float s2 = zd;
            s2 += __shfl_xor_sync(0xffffffffu, s2, 1, 4);
            s2 += __shfl_xor_sync(0xffffffffu, s2, 2, 4);
            c_dn += s2;
            float4 z4 = make_float4(0.f, 0.f, 0.f, 0.f);
            float* obase = out + ((size_t)bh * L_DIM + rming) * L_DIM + jt * JT + lane * 4;
            #pragma unroll 4
            for (int r = 0; r < 16; ++r)
                *(float4*)(obase + (size_t)r * L_DIM) = z4;
        }
    }
}

extern "C" void kernel_launch(void* const* d_in, const int* in_sizes, int n_in,
                              void* d_out, int out_size) {
    const float* k    = (const float*)d_in[0];
    const float* src  = (const float*)d_in[1];
    const float* dest = (const float*)d_in[2];
    float* out = (float*)d_out;

    prep_kernel<<<(N_BH * L_DIM * 4) / NTH, NTH>>>(k, src, dest);

    cudaFuncSetAttribute(mha_fp16,
                         cudaFuncAttributeMaxDynamicSharedMemorySize, SMEM_TOTAL);
    dim3 grid(16, N_BH);
    mha_fp16<<<grid, NTH, SMEM_TOTAL>>>(out);
}

// round 13
// speedup vs baseline: 1.1438x; 1.0627x over previous
#include <cuda_runtime.h>
#include <cuda_fp16.h>
#include <cstdint>

#define L_DIM 2048
#define D_DIM 64
#define N_BH 32
#define ROWS 128
#define JT 128
#define NJT (L_DIM / JT)
#define NTH 256

#define OFF_A 0
#define OFF_B(b) (16384 + (b) * 16384)
#define SMEM_TOTAL 49152

#define NELEM (N_BH * L_DIM * D_DIM)

typedef unsigned long long ull;

// plain (unswizzled) fp16 operands; swizzle applied on cp.async dst
__device__ __align__(16) __half g_A[NELEM];
__device__ __align__(16) __half g_B[NELEM];

__device__ __forceinline__ uint32_t smem_u32(const void* p) {
    uint32_t a;
    asm("{ .reg .u64 t; cvta.to.shared.u64 t, %1; cvt.u32.u64 %0, t; }" : "=r"(a) : "l"(p));
    return a;
}
__device__ __forceinline__ float lg2f(float x) {
    float y; asm("lg2.approx.f32 %0, %1;" : "=f"(y) : "f"(x)); return y;
}
__device__ __forceinline__ float ex2f(float x) {
    float y; asm("ex2.approx.f32 %0, %1;" : "=f"(y) : "f"(x)); return y;
}
__device__ __forceinline__ float pow23_mufu(float a) {
    return ex2f(lg2f(fmaxf(a, 0.0f)) * 0.666666667f);
}
__device__ __forceinline__ ull pk2(float lo, float hi) {
    ull r;
    asm("mov.b64 %0, {%1, %2};" : "=l"(r) : "r"(__float_as_uint(lo)), "r"(__float_as_uint(hi)));
    return r;
}
__device__ __forceinline__ void upk2(ull v, float& lo, float& hi) {
    uint32_t a, b;
    asm("mov.b64 {%0, %1}, %2;" : "=r"(a), "=r"(b) : "l"(v));
    lo = __uint_as_float(a); hi = __uint_as_float(b);
}
__device__ __forceinline__ ull mul2(ull a, ull b) {
    ull d; asm("mul.rn.f32x2 %0, %1, %2;" : "=l"(d) : "l"(a), "l"(b)); return d;
}
__device__ __forceinline__ ull fma2p(ull a, ull b, ull c) {
    ull d; asm("fma.rn.f32x2 %0, %1, %2, %3;" : "=l"(d) : "l"(a), "l"(b), "l"(c)); return d;
}
__device__ __forceinline__ void pow23_fma2(float a, float b, float& ya, float& yb) {
    float xa = fmaxf(a, 0.0f), xb = fmaxf(b, 0.0f);
    float wa = __int_as_float(0x54A2FC96 - (__float_as_int(xa) / 3));
    float wb = __int_as_float(0x54A2FC96 - (__float_as_int(xb) / 3));
    ull x2 = pk2(xa, xb), w2 = pk2(wa, wb);
    const ull m13 = pk2(-1.0f / 3.0f, -1.0f / 3.0f);
    const ull f43 = pk2(4.0f / 3.0f, 4.0f / 3.0f);
    ull t2 = mul2(x2, w2);
    ull r2 = mul2(mul2(t2, w2), w2);
    ull u2 = fma2p(r2, m13, f43);
    w2 = mul2(w2, u2);
    t2 = mul2(x2, w2);
    r2 = mul2(mul2(t2, w2), w2);
    u2 = fma2p(r2, m13, f43);
    ull y2 = mul2(t2, u2);
    upk2(y2, ya, yb);
}
__device__ __forceinline__ void ldsm4(uint32_t* r, uint32_t addr) {
    asm volatile("ldmatrix.sync.aligned.m8n8.x4.shared.b16 {%0,%1,%2,%3}, [%4];"
                 : "=r"(r[0]), "=r"(r[1]), "=r"(r[2]), "=r"(r[3]) : "r"(addr));
}
__device__ __forceinline__ void mma16816(float* c, const uint32_t* a, const uint32_t* b) {
    asm volatile(
        "mma.sync.aligned.m16n8k16.row.col.f32.f16.f16.f32 "
        "{%0,%1,%2,%3}, {%4,%5,%6,%7}, {%8,%9}, {%0,%1,%2,%3};"
        : "+f"(c[0]), "+f"(c[1]), "+f"(c[2]), "+f"(c[3])
        : "r"(a[0]), "r"(a[1]), "r"(a[2]), "r"(a[3]), "r"(b[0]), "r"(b[1]));
}
__device__ __forceinline__ void cpa16(uint32_t dst, const void* src) {
    asm volatile("cp.async.cg.shared.global [%0], [%1], 16;" :: "r"(dst), "l"(src) : "memory");
}
__device__ __forceinline__ void cpa_commit() {
    asm volatile("cp.async.commit_group;" ::: "memory");
}
__device__ __forceinline__ void cpa_wait1() {
    asm volatile("cp.async.wait_group 1;" ::: "memory");
}

// Pre-pass: k*sqrt(src+eps) -> g_A, k*sqrt(dest+eps) -> g_B (plain layout)
__global__ void __launch_bounds__(NTH)
prep_kernel(const float* __restrict__ kin, const float* __restrict__ src,
            const float* __restrict__ dst)
{
    int gid = blockIdx.x * NTH + threadIdx.x;
    int rowg = gid >> 2;
    int q = gid & 3;
    float s = sqrtf(src[rowg] + 1e-12f);
    float d = sqrtf(dst[rowg] + 1e-12f);
    const float* kp = kin + (size_t)rowg * D_DIM + q * 16;
    const size_t rbase = (size_t)rowg * D_DIM;

    #pragma unroll
    for (int g = 0; g < 2; ++g) {
        float4 v0 = *(const float4*)(kp + g * 8);
        float4 v1 = *(const float4*)(kp + g * 8 + 4);
        __half2 a0 = __floats2half2_rn(v0.x * s, v0.y * s);
        __half2 a1 = __floats2half2_rn(v0.z * s, v0.w * s);
        __half2 a2 = __floats2half2_rn(v1.x * s, v1.y * s);
        __half2 a3 = __floats2half2_rn(v1.z * s, v1.w * s);
        __half2 b0 = __floats2half2_rn(v0.x * d, v0.y * d);
        __half2 b1 = __floats2half2_rn(v0.z * d, v0.w * d);
        __half2 b2 = __floats2half2_rn(v1.x * d, v1.y * d);
        __half2 b3 = __floats2half2_rn(v1.z * d, v1.w * d);
        int edst = q * 16 + g * 8;
        *(uint4*)(g_A + rbase + edst) = make_uint4(*(uint32_t*)&a0, *(uint32_t*)&a1,
                                                   *(uint32_t*)&a2, *(uint32_t*)&a3);
        *(uint4*)(g_B + rbase + edst) = make_uint4(*(uint32_t*)&b0, *(uint32_t*)&b1,
                                                   *(uint32_t*)&b2, *(uint32_t*)&b3);
    }
}

// B copy with (1) n-row permutation within each 16-row group so MMA output
// cols are lane-consecutive, (2) SW128 swizzle applied on the smem dst addr.
__device__ __forceinline__ void copyB(uint32_t sbase, int buf, size_t bbase, int jt, int tid)
{
    #pragma unroll
    for (int it = 0; it < 4; ++it) {
        int idx = tid + it * NTH;
        int rowp = idx >> 3, seg = idx & 7;            // physical smem row, 16B seg
        int grp = rowp >> 4;
        int p = rowp & 15;
        int u = p >> 3, w = p & 7;
        int l = (w >> 1) * 4 + u * 2 + (w & 1);        // logical col within group
        int srow = jt * JT + grp * 16 + l;
        uint32_t dst = (uint32_t)(rowp * 128 + ((seg * 16) ^ ((rowp & 7) << 4)));
        cpa16(sbase + OFF_B(buf) + dst, g_B + bbase + (size_t)srow * D_DIM + seg * 8);
    }
}

// Epilogue for one row-half over 64 cols: 4 unit-pairs, each pair = 4
// consecutive logical cols per lane -> in-lane prefix + width-4 scan + STG.128
template <bool MASK>
__device__ __forceinline__ void half_epilogue(
    const float (*acc)[4], int ci,
    float& carry, float* rowp, int jbase, int irow, int q)
{
    const unsigned F = 0xffffffffu;
    float x0[4], p1[4], p2[4], p3[4], sc[4], C[4];
    #pragma unroll
    for (int g = 0; g < 4; ++g) {
        float y0, y1, y2, y3;
        if (g & 1) {
            pow23_fma2(acc[2 * g][ci], acc[2 * g][ci + 1], y0, y1);
            pow23_fma2(acc[2 * g + 1][ci], acc[2 * g + 1][ci + 1], y2, y3);
        } else {
            y0 = pow23_mufu(acc[2 * g][ci]);
            y1 = pow23_mufu(acc[2 * g][ci + 1]);
            y2 = pow23_mufu(acc[2 * g + 1][ci]);
            y3 = pow23_mufu(acc[2 * g + 1][ci + 1]);
        }
        x0[g] = y0;
        p1[g] = y0 + y1;
        p2[g] = p1[g] + y2;
        p3[g] = p2[g] + y3;
        sc[g] = p3[g];
    }
    #pragma unroll
    for (int g = 0; g < 4; ++g) {
        float s1 = __shfl_up_sync(F, sc[g], 1, 4); if (q >= 1) sc[g] += s1;
        float s2 = __shfl_up_sync(F, sc[g], 2, 4); if (q >= 2) sc[g] += s2;
    }
    #pragma unroll
    for (int g = 0; g < 4; ++g)
        C[g] = __shfl_sync(F, sc[g], 3, 4);
    float base = carry;
    #pragma unroll
    for (int g = 0; g < 4; ++g) {
        const int cq = jbase + g * 16 + q * 4;
        float b = base + (sc[g] - p3[g]);
        float4 o;
        if (MASK) {
            o.x = (cq     >= irow) ? b + x0[g] : 0.0f;
            o.y = (cq + 1 >= irow) ? b + p1[g] : 0.0f;
            o.z = (cq + 2 >= irow) ? b + p2[g] : 0.0f;
            o.w = (cq + 3 >= irow) ? b + p3[g] : 0.0f;
        } else {
            o.x = b + x0[g]; o.y = b + p1[g]; o.z = b + p2[g]; o.w = b + p3[g];
        }
        *(float4*)(rowp + cq) = o;
        base += C[g];
    }
    carry = base;
}

__global__ void __launch_bounds__(NTH, 3)
mha_fp16(float* __restrict__ out)
{
    extern __shared__ char smem[];
    const uint32_t sbase = smem_u32(smem);
    const int tid = threadIdx.x;
    const int warp = tid >> 5;
    const int lane = tid & 31;
    const int q = lane & 3;
    const int bh = blockIdx.y;
    const int bxr = blockIdx.x;
    const int low2 = bxr & 3, hi2 = bxr >> 2;
    const int gbase = low2 * 2 + (hi2 >> 1);
    const int bxe = (hi2 & 1) ? (15 - gbase) : gbase;
    const int i0 = bxe * ROWS;

    const size_t khead = (size_t)bh * L_DIM * D_DIM;
    const size_t abase = khead + (size_t)i0 * D_DIM;
    const size_t bbase = khead;

    // A tile (no n-permutation; dst swizzle)
    #pragma unroll
    for (int it = 0; it < 4; ++it) {
        int idx = tid + it * NTH;
        int row = idx >> 3, seg = idx & 7;
        uint32_t dst = (uint32_t)(row * 128 + ((seg * 16) ^ ((row & 7) << 4)));
        cpa16(sbase + OFF_A + dst, g_A + abase + (size_t)row * D_DIM + seg * 8);
    }
    copyB(sbase, 0, bbase, 0, tid);
    cpa_commit();
    copyB(sbase, 1, bbase, 1, tid);
    cpa_commit();

    const int rb = warp * 16;
    const int rming = i0 + rb;
    const int dt = i0 >> 7;
    const int ar0 = rb + ((lane >> 3) & 1) * 8 + (lane & 7);
    const int a_kb = ((lane >> 4) & 1) * 16;
    const int ax   = (ar0 & 7) << 4;
    const int br   = ((lane >> 4) & 1) * 8 + (lane & 7);
    const int b_kb = ((lane >> 3) & 1) * 16;
    const int bx2  = (br & 7) << 4;

    cpa_wait1();
    __syncthreads();

    uint32_t afr[4][4];
    #pragma unroll
    for (int ks = 0; ks < 4; ++ks)
        ldsm4(afr[ks], sbase + OFF_A + ar0 * 128 + (((ks * 32) | a_kb) ^ ax));

    const int iu = rming + (lane >> 2);
    const int idn = iu + 8;
    float* const oru_base = out + ((size_t)bh * L_DIM + iu) * L_DIM;
    float* const ord_base = oru_base + 8 * L_DIM;

    float c_up = 0.0f, c_dn = 0.0f;

    for (int jt = 0; jt < NJT; ++jt) {
        if (jt) { cpa_wait1(); __syncthreads(); }
        const uint32_t B = sbase + OFF_B(jt & 1);
        const bool zt = (jt < dt);
        const bool mt = (jt == dt);
        float zu = 0.f, zd = 0.f;

        #pragma unroll
        for (int h = 0; h < 2; ++h) {
            float acc[8][4];
            #pragma unroll
            for (int n = 0; n < 8; ++n)
                #pragma unroll
                for (int c = 0; c < 4; ++c) acc[n][c] = 0.0f;

            #pragma unroll
            for (int ks = 0; ks < 4; ++ks) {
                const int kb2 = ((ks * 32) | b_kb) ^ bx2;
                #pragma unroll
                for (int cgl = 0; cgl < 4; ++cgl) {
                    const int cg = h * 4 + cgl;
                    uint32_t bf[4];
                    ldsm4(bf, B + (uint32_t)((cg * 16 + br) * 128 + kb2));
                    mma16816(acc[2 * cgl],     afr[ks], bf);
                    mma16816(acc[2 * cgl + 1], afr[ks], bf + 2);
                }
            }

            if (h == 1) {
                __syncthreads();
                if (jt + 2 < NJT) copyB(sbase, jt & 1, bbase, jt + 2, tid);
                cpa_commit();
            }

            if (zt) {
                #pragma unroll
                for (int nb = 0; nb < 8; ++nb) {
                    float y0, y1, z0, z1;
                    if (nb & 1) {
                        pow23_fma2(acc[nb][0], acc[nb][1], y0, y1);
                        pow23_fma2(acc[nb][2], acc[nb][3], z0, z1);
                    } else {
                        y0 = pow23_mufu(acc[nb][0]); y1 = pow23_mufu(acc[nb][1]);
                        z0 = pow23_mufu(acc[nb][2]); z1 = pow23_mufu(acc[nb][3]);
                    }
                    zu += y0 + y1;
                    zd += z0 + z1;
                }
            } else {
                const int jbase = jt * JT + h * 64;
                if (mt) {
                    half_epilogue<true>(acc, 0, c_up, oru_base, jbase, iu, q);
                    half_epilogue<true>(acc, 2, c_dn, ord_base, jbase, idn, q);
                } else {
                    half_epilogue<false>(acc, 0, c_up, oru_base, jbase, iu, q);
                    half_epilogue<false>(acc, 2, c_dn, ord_base, jbase, idn, q);
                }
            }
        }

        if (zt) {
            float t = zu;
            t += __shfl_xor_sync(0xffffffffu, t, 1, 4);
            t += __shfl_xor_sync(0xffffffffu, t, 2, 4);
            c_up += t;
            float s2 = zd;
            s2 += __shfl_xor_sync(0xffffffffu, s2, 1, 4);
            s2 += __shfl_xor_sync(0xffffffffu, s2, 2, 4);
            c_dn += s2;
            float4 z4 = make_float4(0.f, 0.f, 0.f, 0.f);
            float* obase = out + ((size_t)bh * L_DIM + rming) * L_DIM + jt * JT + lane * 4;
            #pragma unroll 4
            for (int r = 0; r < 16; ++r)
                *(float4*)(obase + (size_t)r * L_DIM) = z4;
        }
    }
}

extern "C" void kernel_launch(void* const* d_in, const int* in_sizes, int n_in,
                              void* d_out, int out_size) {
    const float* k    = (const float*)d_in[0];
    const float* src  = (const float*)d_in[1];
    const float* dest = (const float*)d_in[2];
    float* out = (float*)d_out;

    prep_kernel<<<(N_BH * L_DIM * 4) / NTH, NTH>>>(k, src, dest);

    cudaFuncSetAttribute(mha_fp16,
                         cudaFuncAttributeMaxDynamicSharedMemorySize, SMEM_TOTAL);
    dim3 grid(16, N_BH);
    mha_fp16<<<grid, NTH, SMEM_TOTAL>>>(out);
}

// round 14
// speedup vs baseline: 1.1705x; 1.0234x over previous
#include <cuda_runtime.h>
#include <cuda_fp16.h>
#include <cstdint>

#define L_DIM 2048
#define D_DIM 64
#define N_BH 32
#define ROWS 128
#define JT 128
#define NJT (L_DIM / JT)
#define NTH 256

#define OFF_A 0
#define OFF_B(b) (16384 + (b) * 16384)
#define SMEM_TOTAL 49152

#define NELEM (N_BH * L_DIM * D_DIM)

typedef unsigned long long ull;

__device__ __align__(16) __half g_A[NELEM];
__device__ __align__(16) __half g_B[NELEM];

__device__ __forceinline__ uint32_t smem_u32(const void* p) {
    uint32_t a;
    asm("{ .reg .u64 t; cvta.to.shared.u64 t, %1; cvt.u32.u64 %0, t; }" : "=r"(a) : "l"(p));
    return a;
}
__device__ __forceinline__ float lg2f(float x) {
    float y; asm("lg2.approx.f32 %0, %1;" : "=f"(y) : "f"(x)); return y;
}
__device__ __forceinline__ float ex2f(float x) {
    float y; asm("ex2.approx.f32 %0, %1;" : "=f"(y) : "f"(x)); return y;
}
__device__ __forceinline__ float pow23_mufu(float a) {
    return ex2f(lg2f(fmaxf(a, 0.0f)) * 0.666666667f);
}
__device__ __forceinline__ ull pk2(float lo, float hi) {
    ull r;
    asm("mov.b64 %0, {%1, %2};" : "=l"(r) : "r"(__float_as_uint(lo)), "r"(__float_as_uint(hi)));
    return r;
}
__device__ __forceinline__ void upk2(ull v, float& lo, float& hi) {
    uint32_t a, b;
    asm("mov.b64 {%0, %1}, %2;" : "=r"(a), "=r"(b) : "l"(v));
    lo = __uint_as_float(a); hi = __uint_as_float(b);
}
__device__ __forceinline__ ull mul2(ull a, ull b) {
    ull d; asm("mul.rn.f32x2 %0, %1, %2;" : "=l"(d) : "l"(a), "l"(b)); return d;
}
__device__ __forceinline__ ull fma2p(ull a, ull b, ull c) {
    ull d; asm("fma.rn.f32x2 %0, %1, %2, %3;" : "=l"(d) : "l"(a), "l"(b), "l"(c)); return d;
}
__device__ __forceinline__ void pow23_fma2(float a, float b, float& ya, float& yb) {
    float xa = fmaxf(a, 0.0f), xb = fmaxf(b, 0.0f);
    float wa = __int_as_float(0x54A2FC96 - (__float_as_int(xa) / 3));
    float wb = __int_as_float(0x54A2FC96 - (__float_as_int(xb) / 3));
    ull x2 = pk2(xa, xb), w2 = pk2(wa, wb);
    const ull m13 = pk2(-1.0f / 3.0f, -1.0f / 3.0f);
    const ull f43 = pk2(4.0f / 3.0f, 4.0f / 3.0f);
    ull t2 = mul2(x2, w2);
    ull r2 = mul2(mul2(t2, w2), w2);
    ull u2 = fma2p(r2, m13, f43);
    w2 = mul2(w2, u2);
    t2 = mul2(x2, w2);
    r2 = mul2(mul2(t2, w2), w2);
    u2 = fma2p(r2, m13, f43);
    ull y2 = mul2(t2, u2);
    upk2(y2, ya, yb);
}
__device__ __forceinline__ void ldsm4(uint32_t* r, uint32_t addr) {
    asm volatile("ldmatrix.sync.aligned.m8n8.x4.shared.b16 {%0,%1,%2,%3}, [%4];"
                 : "=r"(r[0]), "=r"(r[1]), "=r"(r[2]), "=r"(r[3]) : "r"(addr));
}
__device__ __forceinline__ void mma16816(float* c, const uint32_t* a, const uint32_t* b) {
    asm volatile(
        "mma.sync.aligned.m16n8k16.row.col.f32.f16.f16.f32 "
        "{%0,%1,%2,%3}, {%4,%5,%6,%7}, {%8,%9}, {%0,%1,%2,%3};"
        : "+f"(c[0]), "+f"(c[1]), "+f"(c[2]), "+f"(c[3])
        : "r"(a[0]), "r"(a[1]), "r"(a[2]), "r"(a[3]), "r"(b[0]), "r"(b[1]));
}
__device__ __forceinline__ void cpa16(uint32_t dst, const void* src) {
    asm volatile("cp.async.cg.shared.global [%0], [%1], 16;" :: "r"(dst), "l"(src) : "memory");
}
__device__ __forceinline__ void cpa_commit() {
    asm volatile("cp.async.commit_group;" ::: "memory");
}
__device__ __forceinline__ void cpa_wait1() {
    asm volatile("cp.async.wait_group 1;" ::: "memory");
}

__global__ void __launch_bounds__(NTH)
prep_kernel(const float* __restrict__ kin, const float* __restrict__ src,
            const float* __restrict__ dst)
{
    int gid = blockIdx.x * NTH + threadIdx.x;
    int rowg = gid >> 2;
    int q = gid & 3;
    float s = sqrtf(src[rowg] + 1e-12f);
    float d = sqrtf(dst[rowg] + 1e-12f);
    const float* kp = kin + (size_t)rowg * D_DIM + q * 16;
    const size_t rbase = (size_t)rowg * D_DIM;

    #pragma unroll
    for (int g = 0; g < 2; ++g) {
        float4 v0 = *(const float4*)(kp + g * 8);
        float4 v1 = *(const float4*)(kp + g * 8 + 4);
        __half2 a0 = __floats2half2_rn(v0.x * s, v0.y * s);
        __half2 a1 = __floats2half2_rn(v0.z * s, v0.w * s);
        __half2 a2 = __floats2half2_rn(v1.x * s, v1.y * s);
        __half2 a3 = __floats2half2_rn(v1.z * s, v1.w * s);
        __half2 b0 = __floats2half2_rn(v0.x * d, v0.y * d);
        __half2 b1 = __floats2half2_rn(v0.z * d, v0.w * d);
        __half2 b2 = __floats2half2_rn(v1.x * d, v1.y * d);
        __half2 b3 = __floats2half2_rn(v1.z * d, v1.w * d);
        int edst = q * 16 + g * 8;
        *(uint4*)(g_A + rbase + edst) = make_uint4(*(uint32_t*)&a0, *(uint32_t*)&a1,
                                                   *(uint32_t*)&a2, *(uint32_t*)&a3);
        *(uint4*)(g_B + rbase + edst) = make_uint4(*(uint32_t*)&b0, *(uint32_t*)&b1,
                                                   *(uint32_t*)&b2, *(uint32_t*)&b3);
    }
}

__device__ __forceinline__ void copyB(uint32_t sbase, int buf, size_t bbase, int jt, int tid)
{
    #pragma unroll
    for (int it = 0; it < 4; ++it) {
        int idx = tid + it * NTH;
        int rowp = idx >> 3, seg = idx & 7;
        int grp = rowp >> 4;
        int p = rowp & 15;
        int u = p >> 3, w = p & 7;
        int l = (w >> 1) * 4 + u * 2 + (w & 1);
        int srow = jt * JT + grp * 16 + l;
        uint32_t dst = (uint32_t)(rowp * 128 + ((seg * 16) ^ ((rowp & 7) << 4)));
        cpa16(sbase + OFF_B(buf) + dst, g_B + bbase + (size_t)srow * D_DIM + seg * 8);
    }
}

template <bool MASK>
__device__ __forceinline__ void half_epilogue(
    const float (*acc)[4], int ci,
    float& carry, float* rowp, int jbase, int irow, int q)
{
    const unsigned F = 0xffffffffu;
    float x0[4], p1[4], p2[4], p3[4], sc[4], C[4];
    #pragma unroll
    for (int g = 0; g < 4; ++g) {
        float y0, y1, y2, y3;
        if (g & 1) {
            pow23_fma2(acc[2 * g][ci], acc[2 * g][ci + 1], y0, y1);
            pow23_fma2(acc[2 * g + 1][ci], acc[2 * g + 1][ci + 1], y2, y3);
        } else {
            y0 = pow23_mufu(acc[2 * g][ci]);
            y1 = pow23_mufu(acc[2 * g][ci + 1]);
            y2 = pow23_mufu(acc[2 * g + 1][ci]);
            y3 = pow23_mufu(acc[2 * g + 1][ci + 1]);
        }
        x0[g] = y0;
        p1[g] = y0 + y1;
        p2[g] = p1[g] + y2;
        p3[g] = p2[g] + y3;
        sc[g] = p3[g];
    }
    #pragma unroll
    for (int g = 0; g < 4; ++g) {
        float s1 = __shfl_up_sync(F, sc[g], 1, 4); if (q >= 1) sc[g] += s1;
        float s2 = __shfl_up_sync(F, sc[g], 2, 4); if (q >= 2) sc[g] += s2;
    }
    #pragma unroll
    for (int g = 0; g < 4; ++g)
        C[g] = __shfl_sync(F, sc[g], 3, 4);
    float base = carry;
    #pragma unroll
    for (int g = 0; g < 4; ++g) {
        const int cq = jbase + g * 16 + q * 4;
        float b = base + (sc[g] - p3[g]);
        float4 o;
        if (MASK) {
            o.x = (cq     >= irow) ? b + x0[g] : 0.0f;
            o.y = (cq + 1 >= irow) ? b + p1[g] : 0.0f;
            o.z = (cq + 2 >= irow) ? b + p2[g] : 0.0f;
            o.w = (cq + 3 >= irow) ? b + p3[g] : 0.0f;
        } else {
            o.x = b + x0[g]; o.y = b + p1[g]; o.z = b + p2[g]; o.w = b + p3[g];
        }
        *(float4*)(rowp + cq) = o;
        base += C[g];
    }
    carry = base;
}

__global__ void __launch_bounds__(NTH, 4)
mha_fp16(float* __restrict__ out)
{
    extern __shared__ char smem[];
    const uint32_t sbase = smem_u32(smem);
    const int tid = threadIdx.x;
    const int warp = tid >> 5;
    const int lane = tid & 31;
    const int q = lane & 3;
    // 1D heavy-first grid: low bid = low bxe = heavy (few zero tiles)
    const int bid = blockIdx.x;
    const int bxe = bid >> 5;
    const int bh = bid & 31;
    const int i0 = bxe * ROWS;

    const size_t khead = (size_t)bh * L_DIM * D_DIM;
    const size_t abase = khead + (size_t)i0 * D_DIM;
    const size_t bbase = khead;

    #pragma unroll
    for (int it = 0; it < 4; ++it) {
        int idx = tid + it * NTH;
        int row = idx >> 3, seg = idx & 7;
        uint32_t dst = (uint32_t)(row * 128 + ((seg * 16) ^ ((row & 7) << 4)));
        cpa16(sbase + OFF_A + dst, g_A + abase + (size_t)row * D_DIM + seg * 8);
    }
    copyB(sbase, 0, bbase, 0, tid);
    cpa_commit();
    copyB(sbase, 1, bbase, 1, tid);
    cpa_commit();

    const int rb = warp * 16;
    const int rming = i0 + rb;
    const int dt = i0 >> 7;
    const int ar0 = rb + ((lane >> 3) & 1) * 8 + (lane & 7);
    const int a_kb = ((lane >> 4) & 1) * 16;
    const int ax   = (ar0 & 7) << 4;
    const int br   = ((lane >> 4) & 1) * 8 + (lane & 7);
    const int b_kb = ((lane >> 3) & 1) * 16;
    const int bx2  = (br & 7) << 4;

    cpa_wait1();
    __syncthreads();

    uint32_t afr[4][4];
    #pragma unroll
    for (int ks = 0; ks < 4; ++ks)
        ldsm4(afr[ks], sbase + OFF_A + ar0 * 128 + (((ks * 32) | a_kb) ^ ax));

    const int iu = rming + (lane >> 2);
    const int idn = iu + 8;
    float* const oru_base = out + ((size_t)bh * L_DIM + iu) * L_DIM;
    float* const ord_base = oru_base + 8 * L_DIM;

    float c_up = 0.0f, c_dn = 0.0f;

    for (int jt = 0; jt < NJT; ++jt) {
        if (jt) { cpa_wait1(); __syncthreads(); }
        const uint32_t B = sbase + OFF_B(jt & 1);
        const bool zt = (jt < dt);
        const bool mt = (jt == dt);
        float zu = 0.f, zd = 0.f;

        #pragma unroll
        for (int h = 0; h < 2; ++h) {
            float acc[8][4];
            #pragma unroll
            for (int n = 0; n < 8; ++n)
                #pragma unroll
                for (int c = 0; c < 4; ++c) acc[n][c] = 0.0f;

            #pragma unroll
            for (int ks = 0; ks < 4; ++ks) {
                const int kb2 = ((ks * 32) | b_kb) ^ bx2;
                #pragma unroll
                for (int cgl = 0; cgl < 4; ++cgl) {
                    const int cg = h * 4 + cgl;
                    uint32_t bf[4];
                    ldsm4(bf, B + (uint32_t)((cg * 16 + br) * 128 + kb2));
                    mma16816(acc[2 * cgl],     afr[ks], bf);
                    mma16816(acc[2 * cgl + 1], afr[ks], bf + 2);
                }
            }

            if (h == 1) {
                __syncthreads();
                if (jt + 2 < NJT) copyB(sbase, jt & 1, bbase, jt + 2, tid);
                cpa_commit();
            }

            if (zt) {
                #pragma unroll
                for (int nb = 0; nb < 8; ++nb) {
                    float y0, y1, z0, z1;
                    if (nb & 1) {
                        pow23_fma2(acc[nb][0], acc[nb][1], y0, y1);
                        pow23_fma2(acc[nb][2], acc[nb][3], z0, z1);
                    } else {
                        y0 = pow23_mufu(acc[nb][0]); y1 = pow23_mufu(acc[nb][1]);
                        z0 = pow23_mufu(acc[nb][2]); z1 = pow23_mufu(acc[nb][3]);
                    }
                    zu += y0 + y1;
                    zd += z0 + z1;
                }
            } else {
                const int jbase = jt * JT + h * 64;
                if (mt) {
                    half_epilogue<true>(acc, 0, c_up, oru_base, jbase, iu, q);
                    half_epilogue<true>(acc, 2, c_dn, ord_base, jbase, idn, q);
                } else {
                    half_epilogue<false>(acc, 0, c_up, oru_base, jbase, iu, q);
                    half_epilogue<false>(acc, 2, c_dn, ord_base, jbase, idn, q);
                }
            }
        }

        if (zt) {
            float t = zu;
            t += __shfl_xor_sync(0xffffffffu, t, 1, 4);
            t += __shfl_xor_sync(0xffffffffu, t, 2, 4);
            c_up += t;
            float s2 = zd;
            s2 += __shfl_xor_sync(0xffffffffu, s2, 1, 4);
            s2 += __shfl_xor_sync(0xffffffffu, s2, 2, 4);
            c_dn += s2;
            float4 z4 = make_float4(0.f, 0.f, 0.f, 0.f);
            float* obase = out + ((size_t)bh * L_DIM + rming) * L_DIM + jt * JT + lane * 4;
            #pragma unroll 4
            for (int r = 0; r < 16; ++r)
                *(float4*)(obase + (size_t)r * L_DIM) = z4;
        }
    }
}

extern "C" void kernel_launch(void* const* d_in, const int* in_sizes, int n_in,
                              void* d_out, int out_size) {
    const float* k    = (const float*)d_in[0];
    const float* src  = (const float*)d_in[1];
    const float* dest = (const float*)d_in[2];
    float* out = (float*)d_out;

    prep_kernel<<<(N_BH * L_DIM * 4) / NTH, NTH>>>(k, src, dest);

    cudaFuncSetAttribute(mha_fp16,
                         cudaFuncAttributeMaxDynamicSharedMemorySize, SMEM_TOTAL);
    mha_fp16<<<512, NTH, SMEM_TOTAL>>>(out);
}

// round 15
// speedup vs baseline: 1.2744x; 1.0888x over previous
#include <cuda_runtime.h>
#include <cuda_fp16.h>
#include <cstdint>

#define L_DIM 2048
#define D_DIM 64
#define N_BH 32
#define ROWS 128
#define JT 128
#define NJT (L_DIM / JT)
#define NTH 256

#define OFF_A 0
#define OFF_B(b) (16384 + (b) * 16384)
#define SMEM_TOTAL 49152

#define NELEM (N_BH * L_DIM * D_DIM)

__device__ __align__(16) __half g_A[NELEM];
__device__ __align__(16) __half g_B[NELEM];

__device__ __forceinline__ uint32_t smem_u32(const void* p) {
    uint32_t a;
    asm("{ .reg .u64 t; cvta.to.shared.u64 t, %1; cvt.u32.u64 %0, t; }" : "=r"(a) : "l"(p));
    return a;
}
__device__ __forceinline__ float lg2f(float x) {
    float y; asm("lg2.approx.f32 %0, %1;" : "=f"(y) : "f"(x)); return y;
}
__device__ __forceinline__ float ex2f(float x) {
    float y; asm("ex2.approx.f32 %0, %1;" : "=f"(y) : "f"(x)); return y;
}
// (relu(a))^(2/3), all-MUFU: 4 instrs/elem (max, lg2, mul, ex2)
__device__ __forceinline__ float pow23(float a) {
    return ex2f(lg2f(fmaxf(a, 0.0f)) * 0.666666667f);
}
__device__ __forceinline__ void ldsm4(uint32_t* r, uint32_t addr) {
    asm volatile("ldmatrix.sync.aligned.m8n8.x4.shared.b16 {%0,%1,%2,%3}, [%4];"
                 : "=r"(r[0]), "=r"(r[1]), "=r"(r[2]), "=r"(r[3]) : "r"(addr));
}
__device__ __forceinline__ void mma16816(float* c, const uint32_t* a, const uint32_t* b) {
    asm volatile(
        "mma.sync.aligned.m16n8k16.row.col.f32.f16.f16.f32 "
        "{%0,%1,%2,%3}, {%4,%5,%6,%7}, {%8,%9}, {%0,%1,%2,%3};"
        : "+f"(c[0]), "+f"(c[1]), "+f"(c[2]), "+f"(c[3])
        : "r"(a[0]), "r"(a[1]), "r"(a[2]), "r"(a[3]), "r"(b[0]), "r"(b[1]));
}
__device__ __forceinline__ void cpa16(uint32_t dst, const void* src) {
    asm volatile("cp.async.cg.shared.global [%0], [%1], 16;" :: "r"(dst), "l"(src) : "memory");
}
__device__ __forceinline__ void cpa_commit() {
    asm volatile("cp.async.commit_group;" ::: "memory");
}
__device__ __forceinline__ void cpa_wait1() {
    asm volatile("cp.async.wait_group 1;" ::: "memory");
}

__global__ void __launch_bounds__(NTH)
prep_kernel(const float* __restrict__ kin, const float* __restrict__ src,
            const float* __restrict__ dst)
{
    int gid = blockIdx.x * NTH + threadIdx.x;
    int rowg = gid >> 2;
    int q = gid & 3;
    float s = sqrtf(src[rowg] + 1e-12f);
    float d = sqrtf(dst[rowg] + 1e-12f);
    const float* kp = kin + (size_t)rowg * D_DIM + q * 16;
    const size_t rbase = (size_t)rowg * D_DIM;

    #pragma unroll
    for (int g = 0; g < 2; ++g) {
        float4 v0 = *(const float4*)(kp + g * 8);
        float4 v1 = *(const float4*)(kp + g * 8 + 4);
        __half2 a0 = __floats2half2_rn(v0.x * s, v0.y * s);
        __half2 a1 = __floats2half2_rn(v0.z * s, v0.w * s);
        __half2 a2 = __floats2half2_rn(v1.x * s, v1.y * s);
        __half2 a3 = __floats2half2_rn(v1.z * s, v1.w * s);
        __half2 b0 = __floats2half2_rn(v0.x * d, v0.y * d);
        __half2 b1 = __floats2half2_rn(v0.z * d, v0.w * d);
        __half2 b2 = __floats2half2_rn(v1.x * d, v1.y * d);
        __half2 b3 = __floats2half2_rn(v1.z * d, v1.w * d);
        int edst = q * 16 + g * 8;
        *(uint4*)(g_A + rbase + edst) = make_uint4(*(uint32_t*)&a0, *(uint32_t*)&a1,
                                                   *(uint32_t*)&a2, *(uint32_t*)&a3);
        *(uint4*)(g_B + rbase + edst) = make_uint4(*(uint32_t*)&b0, *(uint32_t*)&b1,
                                                   *(uint32_t*)&b2, *(uint32_t*)&b3);
    }
}

__device__ __forceinline__ void copyB(uint32_t sbase, int buf, size_t bbase, int jt, int tid)
{
    #pragma unroll
    for (int it = 0; it < 4; ++it) {
        int idx = tid + it * NTH;
        int rowp = idx >> 3, seg = idx & 7;
        int grp = rowp >> 4;
        int p = rowp & 15;
        int u = p >> 3, w = p & 7;
        int l = (w >> 1) * 4 + u * 2 + (w & 1);
        int srow = jt * JT + grp * 16 + l;
        uint32_t dst = (uint32_t)(rowp * 128 + ((seg * 16) ^ ((rowp & 7) << 4)));
        cpa16(sbase + OFF_B(buf) + dst, g_B + bbase + (size_t)srow * D_DIM + seg * 8);
    }
}

template <bool MASK>
__device__ __forceinline__ void half_epilogue(
    const float (*acc)[4], int ci,
    float& carry, float* rowp, int jbase, int irow, int q)
{
    const unsigned F = 0xffffffffu;
    float x0[4], p1[4], p2[4], p3[4], sc[4], C[4];
    #pragma unroll
    for (int g = 0; g < 4; ++g) {
        float y0 = pow23(acc[2 * g][ci]);
        float y1 = pow23(acc[2 * g][ci + 1]);
        float y2 = pow23(acc[2 * g + 1][ci]);
        float y3 = pow23(acc[2 * g + 1][ci + 1]);
        x0[g] = y0;
        p1[g] = y0 + y1;
        p2[g] = p1[g] + y2;
        p3[g] = p2[g] + y3;
        sc[g] = p3[g];
    }
    #pragma unroll
    for (int g = 0; g < 4; ++g) {
        float s1 = __shfl_up_sync(F, sc[g], 1, 4); if (q >= 1) sc[g] += s1;
        float s2 = __shfl_up_sync(F, sc[g], 2, 4); if (q >= 2) sc[g] += s2;
    }
    #pragma unroll
    for (int g = 0; g < 4; ++g)
        C[g] = __shfl_sync(F, sc[g], 3, 4);
    float base = carry;
    #pragma unroll
    for (int g = 0; g < 4; ++g) {
        const int cq = jbase + g * 16 + q * 4;
        float b = base + (sc[g] - p3[g]);
        float4 o;
        if (MASK) {
            o.x = (cq     >= irow) ? b + x0[g] : 0.0f;
            o.y = (cq + 1 >= irow) ? b + p1[g] : 0.0f;
            o.z = (cq + 2 >= irow) ? b + p2[g] : 0.0f;
            o.w = (cq + 3 >= irow) ? b + p3[g] : 0.0f;
        } else {
            o.x = b + x0[g]; o.y = b + p1[g]; o.z = b + p2[g]; o.w = b + p3[g];
        }
        *(float4*)(rowp + cq) = o;
        base += C[g];
    }
    carry = base;
}

__global__ void __launch_bounds__(NTH, 4)
mha_fp16(float* __restrict__ out)
{
    extern __shared__ char smem[];
    const uint32_t sbase = smem_u32(smem);
    const int tid = threadIdx.x;
    const int warp = tid >> 5;
    const int lane = tid & 31;
    const int q = lane & 3;
    const int bid = blockIdx.x;
    const int bxe = bid >> 5;
    const int bh = bid & 31;
    const int i0 = bxe * ROWS;

    const size_t khead = (size_t)bh * L_DIM * D_DIM;
    const size_t abase = khead + (size_t)i0 * D_DIM;
    const size_t bbase = khead;

    #pragma unroll
    for (int it = 0; it < 4; ++it) {
        int idx = tid + it * NTH;
        int row = idx >> 3, seg = idx & 7;
        uint32_t dst = (uint32_t)(row * 128 + ((seg * 16) ^ ((row & 7) << 4)));
        cpa16(sbase + OFF_A + dst, g_A + abase + (size_t)row * D_DIM + seg * 8);
    }
    copyB(sbase, 0, bbase, 0, tid);
    cpa_commit();
    copyB(sbase, 1, bbase, 1, tid);
    cpa_commit();

    const int rb = warp * 16;
    const int rming = i0 + rb;
    const int dt = i0 >> 7;
    const int ar0 = rb + ((lane >> 3) & 1) * 8 + (lane & 7);
    const int a_kb = ((lane >> 4) & 1) * 16;
    const int ax   = (ar0 & 7) << 4;
    const int br   = ((lane >> 4) & 1) * 8 + (lane & 7);
    const int b_kb = ((lane >> 3) & 1) * 16;
    const int bx2  = (br & 7) << 4;

    cpa_wait1();
    __syncthreads();

    uint32_t afr[4][4];
    #pragma unroll
    for (int ks = 0; ks < 4; ++ks)
        ldsm4(afr[ks], sbase + OFF_A + ar0 * 128 + (((ks * 32) | a_kb) ^ ax));

    const int iu = rming + (lane >> 2);
    const int idn = iu + 8;
    float* const oru_base = out + ((size_t)bh * L_DIM + iu) * L_DIM;
    float* const ord_base = oru_base + 8 * L_DIM;

    float c_up = 0.0f, c_dn = 0.0f;

    for (int jt = 0; jt < NJT; ++jt) {
        if (jt) { cpa_wait1(); __syncthreads(); }
        const uint32_t B = sbase + OFF_B(jt & 1);
        const bool zt = (jt < dt);
        const bool mt = (jt == dt);
        float zu = 0.f, zd = 0.f;

        #pragma unroll
        for (int h = 0; h < 2; ++h) {
            float acc[8][4];
            #pragma unroll
            for (int n = 0; n < 8; ++n)
                #pragma unroll
                for (int c = 0; c < 4; ++c) acc[n][c] = 0.0f;

            #pragma unroll
            for (int ks = 0; ks < 4; ++ks) {
                const int kb2 = ((ks * 32) | b_kb) ^ bx2;
                #pragma unroll
                for (int cgl = 0; cgl < 4; ++cgl) {
                    const int cg = h * 4 + cgl;
                    uint32_t bf[4];
                    ldsm4(bf, B + (uint32_t)((cg * 16 + br) * 128 + kb2));
                    mma16816(acc[2 * cgl],     afr[ks], bf);
                    mma16816(acc[2 * cgl + 1], afr[ks], bf + 2);
                }
            }

            if (h == 1) {
                __syncthreads();
                if (jt + 2 < NJT) copyB(sbase, jt & 1, bbase, jt + 2, tid);
                cpa_commit();
            }

            if (zt) {
                #pragma unroll
                for (int nb = 0; nb < 8; ++nb) {
                    zu += pow23(acc[nb][0]) + pow23(acc[nb][1]);
                    zd += pow23(acc[nb][2]) + pow23(acc[nb][3]);
                }
            } else {
                const int jbase = jt * JT + h * 64;
                if (mt) {
                    half_epilogue<true>(acc, 0, c_up, oru_base, jbase, iu, q);
                    half_epilogue<true>(acc, 2, c_dn, ord_base, jbase, idn, q);
                } else {
                    half_epilogue<false>(acc, 0, c_up, oru_base, jbase, iu, q);
                    half_epilogue<false>(acc, 2, c_dn, ord_base, jbase, idn, q);
                }
            }
        }

        if (zt) {
            float t = zu;
            t += __shfl_xor_sync(0xffffffffu, t, 1, 4);
            t += __shfl_xor_sync(0xffffffffu, t, 2, 4);
            c_up += t;
            float s2 = zd;
            s2 += __shfl_xor_sync(0xffffffffu, s2, 1, 4);
            s2 += __shfl_xor_sync(0xffffffffu, s2, 2, 4);
            c_dn += s2;
            float4 z4 = make_float4(0.f, 0.f, 0.f, 0.f);
            float* obase = out + ((size_t)bh * L_DIM + rming) * L_DIM + jt * JT + lane * 4;
            #pragma unroll 4
            for (int r = 0; r < 16; ++r)
                *(float4*)(obase + (size_t)r * L_DIM) = z4;
        }
    }
}

extern "C" void kernel_launch(void* const* d_in, const int* in_sizes, int n_in,
                              void* d_out, int out_size) {
    const float* k    = (const float*)d_in[0];
    const float* src  = (const float*)d_in[1];
    const float* dest = (const float*)d_in[2];
    float* out = (float*)d_out;

    prep_kernel<<<(N_BH * L_DIM * 4) / NTH, NTH>>>(k, src, dest);

    cudaFuncSetAttribute(mha_fp16,
                         cudaFuncAttributeMaxDynamicSharedMemorySize, SMEM_TOTAL);
    mha_fp16<<<512, NTH, SMEM_TOTAL>>>(out);
}